// round 14
// baseline (speedup 1.0000x reference)
#include <cuda_runtime.h>
#include <cuda.h>
#include <cuda_fp16.h>
#include <cstdint>
#include <cstddef>

// Problem constants
#define NB 4
#define NS 8192
#define ND 1024
#define NH 8
#define NDK 128
#define NE 129
#define NM 32768
#define KFC 1032

// ---------------- scratch (static device globals; no allocations) ----------
static __device__ float g_pa[532512];       // (32, 129, 129) p_attn
static __device__ float g_gpos[4096];       // (B, 1024) pos-column of G (sum over h)
static __device__ float g_bias2[4096];      // (B, 1024) folded bias
static __device__ __half g_a16[33554432];   // key fp16 / Gd hi+lo / query fp16
static __device__ __half g_c16[33554432];   // value fp16
static __device__ __half g_bh16[4227072];   // B hi (Wk+Wv / Wq hi)
static __device__ __half g_bl16[4227072];   // B lo (Wq lo for gemm3)
static __device__ __half g_k16[33554432];   // LN'd K, head-major (bh,s,d) fp16
static __device__ __half g_vh16[33554432];  // LN'd V, head-major fp16
static __device__ __half g_wc16[4194304];   // Wcomb fp16 (B,1024,1024)

// ============================ PTX helpers ==================================
__device__ __forceinline__ uint32_t smem_u32(const void* p) {
    uint32_t a;
    asm("{ .reg .u64 t; cvta.to.shared.u64 t, %1; cvt.u32.u64 %0, t; }"
        : "=r"(a) : "l"(p));
    return a;
}
__device__ __forceinline__ void mbar_init(uint32_t mbar, uint32_t cnt) {
    asm volatile("mbarrier.init.shared.b64 [%0], %1;" :: "r"(mbar), "r"(cnt) : "memory");
}
__device__ __forceinline__ void mbar_expect_tx(uint32_t mbar, uint32_t bytes) {
    asm volatile("mbarrier.arrive.expect_tx.shared.b64 _, [%0], %1;"
                 :: "r"(mbar), "r"(bytes) : "memory");
}
__device__ __forceinline__ void mbar_arrive(uint32_t mbar) {
    asm volatile("mbarrier.arrive.shared.b64 _, [%0];" :: "r"(mbar) : "memory");
}
__device__ __forceinline__ void mbar_wait(uint32_t mbar, uint32_t parity) {
    asm volatile(
        "{\n\t.reg .pred P;\n\t"
        "BWL_%=:\n\t"
        "mbarrier.try_wait.parity.acquire.cta.shared::cta.b64 P, [%0], %1, 0x989680;\n\t"
        "@P bra.uni BWD_%=;\n\t"
        "bra.uni BWL_%=;\n\t"
        "BWD_%=:\n\t}"
        :: "r"(mbar), "r"(parity) : "memory");
}
__device__ __forceinline__ void tma_load_3d(uint32_t dst, const CUtensorMap* tm,
                                            int x, int y, int z, uint32_t mbar) {
    asm volatile(
        "cp.async.bulk.tensor.3d.shared::cta.global.tile.mbarrier::complete_tx::bytes "
        "[%0], [%1, {%2, %3, %4}], [%5];"
        :: "r"(dst), "l"(tm), "r"(x), "r"(y), "r"(z), "r"(mbar) : "memory");
}
__device__ __forceinline__ void fence_async_shared() {
    asm volatile("fence.proxy.async.shared::cta;" ::: "memory");
}
__device__ __forceinline__ void ldsm4(uint32_t* r, uint32_t addr) {
    asm volatile("ldmatrix.sync.aligned.m8n8.x4.shared.b16 {%0,%1,%2,%3}, [%4];"
                 : "=r"(r[0]), "=r"(r[1]), "=r"(r[2]), "=r"(r[3]) : "r"(addr));
}
__device__ __forceinline__ void ldsm4t(uint32_t* r, uint32_t addr) {
    asm volatile("ldmatrix.sync.aligned.m8n8.x4.trans.shared.b16 {%0,%1,%2,%3}, [%4];"
                 : "=r"(r[0]), "=r"(r[1]), "=r"(r[2]), "=r"(r[3]) : "r"(addr));
}
__device__ __forceinline__ void mma_f16(float* c, const uint32_t* a, const uint32_t* b) {
    asm volatile(
        "mma.sync.aligned.m16n8k16.row.col.f32.f16.f16.f32 "
        "{%0,%1,%2,%3}, {%4,%5,%6,%7}, {%8,%9}, {%0,%1,%2,%3};"
        : "+f"(c[0]), "+f"(c[1]), "+f"(c[2]), "+f"(c[3])
        : "r"(a[0]), "r"(a[1]), "r"(a[2]), "r"(a[3]), "r"(b[0]), "r"(b[1]));
}
__device__ __forceinline__ uint32_t swz(uint32_t base, int r, int c) {
    return base + r * 128 + (c ^ ((r & 7) << 4));
}

// ============================ GEMM constants ===============================
static constexpr uint32_t OPA_BYTES = 128 * 64 * 2;   // 16 KB
static constexpr uint32_t OPB_BYTES = 256 * 64 * 2;   // 32 KB
static constexpr uint32_t STG_BYTES = OPA_BYTES + OPB_BYTES;  // 48 KB
static constexpr uint32_t CTRL_BYTES = 1024;
static constexpr int ST = 4;
static constexpr uint32_t STAGES_END = CTRL_BYTES + ST * STG_BYTES;   // 197632
static constexpr uint32_t SMEM_KV = STAGES_END + 16384 + 2048;        // 216064
static constexpr uint32_t SMEM_OUT = STAGES_END;                      // 197632
// g_kernel smem: pat [129][132] + wt [129][68]
static constexpr uint32_t SMEM_G = (129 * 132 + 129 * 68) * 4;        // 103200

// ============================ K/V projection + fused LN ====================
// grid (4 nblk, 256 m-tiles, 2 kv), 288 threads (8 compute + producer warp).
__global__ __launch_bounds__(288, 1) void gemm_kv(
    const __grid_constant__ CUtensorMap tmAK,
    const __grid_constant__ CUtensorMap tmAV,
    const __grid_constant__ CUtensorMap tmB,    // batched (z: 0=Wk, 1=Wv)
    const float* __restrict__ bk, const float* __restrict__ bv,
    const float* __restrict__ gK, const float* __restrict__ betaK,
    const float* __restrict__ gV, const float* __restrict__ betaV,
    __half* __restrict__ k16, __half* __restrict__ vh16)
{
    extern __shared__ __align__(1024) char smem[];
    const uint32_t sb = smem_u32(smem);
    const int tid = threadIdx.x;
    const int wid = tid >> 5, lane = tid & 31;
    const int warp_row = wid >> 2;
    const int warp_col = wid & 3;
    const bool producer = (wid == 8);

    const uint32_t full0  = sb;
    const uint32_t empty0 = sb + 128;
    const uint32_t tiles  = sb + CTRL_BYTES;

    const int nblk = blockIdx.x;
    const int n0g = nblk * 256;
    const int m0 = blockIdx.y * 128;
    const int zKV = blockIdx.z;
    const CUtensorMap* tmA = zKV ? &tmAV : &tmAK;
    const int KB = 16;

    if (tid == 0) {
        for (int s = 0; s < ST; s++) {
            mbar_init(full0 + s * 8, 1);
            mbar_init(empty0 + s * 8, 256);
        }
        fence_async_shared();
    }
    __syncthreads();

    float acc[4][8][4];
#pragma unroll
    for (int mi = 0; mi < 4; mi++)
#pragma unroll
        for (int ni = 0; ni < 8; ni++)
#pragma unroll
            for (int q = 0; q < 4; q++) acc[mi][ni][q] = 0.f;

    if (producer) {
        if (lane == 0) {
            for (int s = 0; s < ST; s++) {
                uint32_t fb = full0 + s * 8;
                mbar_expect_tx(fb, STG_BYTES);
                uint32_t a0 = tiles + s * STG_BYTES;
                tma_load_3d(a0,             tmA,  s * 64, m0,  0,   fb);
                tma_load_3d(a0 + OPA_BYTES, &tmB, s * 64, n0g, zKV, fb);
            }
            for (int kb = ST; kb < KB; kb++) {
                int s = kb % ST;
                mbar_wait(empty0 + s * 8, (uint32_t)(((kb - ST) / ST) & 1));
                uint32_t fb = full0 + s * 8;
                mbar_expect_tx(fb, STG_BYTES);
                uint32_t a0 = tiles + s * STG_BYTES;
                tma_load_3d(a0,             tmA,  kb * 64, m0,  0,   fb);
                tma_load_3d(a0 + OPA_BYTES, &tmB, kb * 64, n0g, zKV, fb);
            }
        }
    } else {
        const int aR = lane & 15;
        const int aC = (lane >> 4) << 4;
        const int bR = ((lane >> 4) << 3) + (lane & 7);
        const int bC = ((lane >> 3) & 1) << 4;

        for (int kb = 0; kb < KB; kb++) {
            const int s = kb % ST;
            mbar_wait(full0 + s * 8, (uint32_t)((kb / ST) & 1));

            const uint32_t A0 = tiles + s * STG_BYTES;
            const uint32_t B0 = A0 + OPA_BYTES;

#pragma unroll
            for (int ki = 0; ki < 4; ki++) {
                const int kc = ki * 32;
                uint32_t af[4][4], bhi[8][2];
#pragma unroll
                for (int mi = 0; mi < 4; mi++) {
                    int r = warp_row * 64 + mi * 16 + aR;
                    ldsm4(af[mi], swz(A0, r, kc + aC));
                }
#pragma unroll
                for (int g = 0; g < 4; g++) {
                    int r = warp_col * 64 + g * 16 + bR;
                    uint32_t tr[4];
                    ldsm4(tr, swz(B0, r, kc + bC));
                    bhi[2 * g][0] = tr[0]; bhi[2 * g][1] = tr[1];
                    bhi[2 * g + 1][0] = tr[2]; bhi[2 * g + 1][1] = tr[3];
                }
                if (ki == 3) mbar_arrive(empty0 + s * 8);
#pragma unroll
                for (int mi = 0; mi < 4; mi++)
#pragma unroll
                    for (int ni = 0; ni < 8; ni++)
                        mma_f16(acc[mi][ni], af[mi], bhi[ni]);
            }
        }
    }

    // ---- fused LN epilogue ----
    __syncthreads();

    float2* part  = (float2*)(smem + STAGES_END);           // [128][16]
    float2* stats = (float2*)(smem + STAGES_END + 16384);   // [128][2]

    const float* biasp = zKV ? bv : bk;
    const float* gsel  = zKV ? gV : gK;
    const float* besel = zKV ? betaV : betaK;
    __half* outp = zKV ? vh16 : k16;
    const int hh = warp_col >> 1;

    if (!producer) {
        const int slot = warp_col * 4 + (lane & 3);
#pragma unroll
        for (int mi = 0; mi < 4; mi++) {
#pragma unroll
            for (int ni = 0; ni < 8; ni++) {
                int col = warp_col * 64 + ni * 8 + (lane & 3) * 2;
                float b0v = biasp[n0g + col], b1v = biasp[n0g + col + 1];
                acc[mi][ni][0] += b0v; acc[mi][ni][1] += b1v;
                acc[mi][ni][2] += b0v; acc[mi][ni][3] += b1v;
            }
#pragma unroll
            for (int half = 0; half < 2; half++) {
                float s = 0.f, sq = 0.f;
#pragma unroll
                for (int ni = 0; ni < 8; ni++) {
                    float v0 = acc[mi][ni][half * 2 + 0];
                    float v1 = acc[mi][ni][half * 2 + 1];
                    s += v0 + v1;
                    sq += v0 * v0 + v1 * v1;
                }
                int r = warp_row * 64 + mi * 16 + (lane >> 2) + half * 8;
                part[r * 16 + slot] = make_float2(s, sq);
            }
        }
    }
    __syncthreads();
    if (tid < 256) {
        int r = tid >> 1, hsel = tid & 1;
        float s = 0.f, sq = 0.f;
#pragma unroll
        for (int i = 0; i < 8; i++) {
            float2 p = part[r * 16 + hsel * 8 + i];
            s += p.x; sq += p.y;
        }
        float mean = s * (1.f / 128.f);
        float var  = sq * (1.f / 128.f) - mean * mean;
        stats[r * 2 + hsel] = make_float2(mean, rsqrtf(var + 1e-5f));
    }
    __syncthreads();

    if (!producer) {
#pragma unroll
        for (int mi = 0; mi < 4; mi++) {
#pragma unroll
            for (int half = 0; half < 2; half++) {
                int r = warp_row * 64 + mi * 16 + (lane >> 2) + half * 8;
                float2 st = stats[r * 2 + hh];
                int m = m0 + r;
                int b = m >> 13, sIdx = m & 8191;
                size_t base = (((size_t)(b * NH + nblk * 2 + hh)) * NS + sIdx) * NDK;
#pragma unroll
                for (int ni = 0; ni < 8; ni++) {
                    int col = warp_col * 64 + ni * 8 + (lane & 3) * 2;
                    int c128 = col & 127;
                    float gg0 = gsel[n0g + col],  gg1 = gsel[n0g + col + 1];
                    float be0 = besel[n0g + col], be1 = besel[n0g + col + 1];
                    float y0 = (acc[mi][ni][half * 2 + 0] - st.x) * st.y * gg0 + be0;
                    float y1 = (acc[mi][ni][half * 2 + 1] - st.x) * st.y * gg1 + be1;
                    *(__half2*)(outp + base + c128) =
                        __half2(__float2half_rn(y0), __float2half_rn(y1));
                }
            }
        }
    }
}

// ============================ final GEMM (BN=256) ==========================
__global__ __launch_bounds__(288, 1) void gemm_out(
    const __grid_constant__ CUtensorMap tmA,
    const __grid_constant__ CUtensorMap tmB,
    const float* __restrict__ bias2,
    const float* __restrict__ posv,
    const float* __restrict__ gposv,
    float* __restrict__ C)
{
    extern __shared__ __align__(1024) char smem[];
    const uint32_t sb = smem_u32(smem);
    const int tid = threadIdx.x;
    const int wid = tid >> 5, lane = tid & 31;
    const int warp_row = wid >> 2;
    const int warp_col = wid & 3;
    const bool producer = (wid == 8);

    const uint32_t full0  = sb;
    const uint32_t empty0 = sb + 128;
    const uint32_t tiles  = sb + CTRL_BYTES;

    const int n0 = blockIdx.x * 256;
    const int zB = blockIdx.z;
    const int m0 = zB * 8192 + blockIdx.y * 128;
    const int KB = 16;

    if (tid == 0) {
        for (int s = 0; s < ST; s++) {
            mbar_init(full0 + s * 8, 1);
            mbar_init(empty0 + s * 8, 256);
        }
        fence_async_shared();
    }
    __syncthreads();

    if (producer) {
        if (lane == 0) {
            for (int s = 0; s < ST; s++) {
                uint32_t fb = full0 + s * 8;
                mbar_expect_tx(fb, STG_BYTES);
                uint32_t a0 = tiles + s * STG_BYTES;
                tma_load_3d(a0,             &tmA, s * 64, m0, 0,  fb);
                tma_load_3d(a0 + OPA_BYTES, &tmB, s * 64, n0, zB, fb);
            }
            for (int kb = ST; kb < KB; kb++) {
                int s = kb % ST;
                mbar_wait(empty0 + s * 8, (uint32_t)(((kb - ST) / ST) & 1));
                uint32_t fb = full0 + s * 8;
                mbar_expect_tx(fb, STG_BYTES);
                uint32_t a0 = tiles + s * STG_BYTES;
                tma_load_3d(a0,             &tmA, kb * 64, m0, 0,  fb);
                tma_load_3d(a0 + OPA_BYTES, &tmB, kb * 64, n0, zB, fb);
            }
        }
        return;
    }

    float acc[4][8][4];
#pragma unroll
    for (int mi = 0; mi < 4; mi++)
#pragma unroll
        for (int ni = 0; ni < 8; ni++)
#pragma unroll
            for (int q = 0; q < 4; q++) acc[mi][ni][q] = 0.f;

    const int aR = lane & 15;
    const int aC = (lane >> 4) << 4;
    const int bR = ((lane >> 4) << 3) + (lane & 7);
    const int bC = ((lane >> 3) & 1) << 4;

    for (int kb = 0; kb < KB; kb++) {
        const int s = kb % ST;
        mbar_wait(full0 + s * 8, (uint32_t)((kb / ST) & 1));

        const uint32_t A0 = tiles + s * STG_BYTES;
        const uint32_t B0 = A0 + OPA_BYTES;

#pragma unroll
        for (int ki = 0; ki < 4; ki++) {
            const int kc = ki * 32;
            uint32_t af[4][4], bhi[8][2];
#pragma unroll
            for (int mi = 0; mi < 4; mi++) {
                int r = warp_row * 64 + mi * 16 + aR;
                ldsm4(af[mi], swz(A0, r, kc + aC));
            }
#pragma unroll
            for (int g = 0; g < 4; g++) {
                int r = warp_col * 64 + g * 16 + bR;
                uint32_t tr[4];
                ldsm4(tr, swz(B0, r, kc + bC));
                bhi[2 * g][0] = tr[0]; bhi[2 * g][1] = tr[1];
                bhi[2 * g + 1][0] = tr[2]; bhi[2 * g + 1][1] = tr[3];
            }
            if (ki == 3) mbar_arrive(empty0 + s * 8);
#pragma unroll
            for (int mi = 0; mi < 4; mi++)
#pragma unroll
                for (int ni = 0; ni < 8; ni++)
                    mma_f16(acc[mi][ni], af[mi], bhi[ni]);
        }
    }

    const float* biasp = bias2 + zB * 1024;
    const float* gpp   = gposv + zB * 1024;

#pragma unroll
    for (int mi = 0; mi < 4; mi++) {
        int r = m0 + warp_row * 64 + mi * 16 + (lane >> 2);
        float pv = posv[r];
        float pv2 = posv[r + 8];
#pragma unroll
        for (int ni = 0; ni < 8; ni++) {
            int cc = n0 + warp_col * 64 + ni * 8 + (lane & 3) * 2;
            float b0v = biasp[cc], b1v = biasp[cc + 1];
            float g0 = gpp[cc], g1 = gpp[cc + 1];
            float2 v0 = { acc[mi][ni][0] + b0v + pv * g0,
                          acc[mi][ni][1] + b1v + pv * g1 };
            float2 v1 = { acc[mi][ni][2] + b0v + pv2 * g0,
                          acc[mi][ni][3] + b1v + pv2 * g1 };
            *(float2*)(C + (size_t)r * 1024 + cc) = v0;
            *(float2*)(C + (size_t)(r + 8) * 1024 + cc) = v1;
        }
    }
}

// ============================ 3-pass GEMM (A hi/lo, B hi/lo) ===============
static constexpr int ST3 = 3;
static constexpr uint32_t OP_BYTES = 128 * 64 * 2;
static constexpr uint32_t STG3_BYTES = 4 * OP_BYTES;
static constexpr uint32_t SMEM3_DYN = CTRL_BYTES + ST3 * STG3_BYTES;

__global__ __launch_bounds__(256, 1) void gemm_mma3(
    const __grid_constant__ CUtensorMap tmAhi,
    const __grid_constant__ CUtensorMap tmAlo,
    const __grid_constant__ CUtensorMap tmBhi,
    const __grid_constant__ CUtensorMap tmBlo,
    __half* __restrict__ Cout, int KB)
{
    extern __shared__ __align__(1024) char smem[];
    const uint32_t sb = smem_u32(smem);
    const int tid = threadIdx.x;
    const int wid = tid >> 5, lane = tid & 31;
    const int warp_row = wid >> 2;
    const int warp_col = wid & 3;

    const uint32_t full0  = sb;
    const uint32_t empty0 = sb + 128;
    const uint32_t tiles  = sb + CTRL_BYTES;

    const int n0 = blockIdx.x * 128;
    const int aY = blockIdx.y * 128;
    const int aZ = blockIdx.z;
    const int m0 = blockIdx.z * 1024 + aY;

    if (tid == 0) {
        for (int s = 0; s < ST3; s++) {
            mbar_init(full0 + s * 8, 1);
            mbar_init(empty0 + s * 8, 256);
        }
        fence_async_shared();
    }
    __syncthreads();

    if (tid == 0) {
        for (int s = 0; s < ST3; s++) {
            uint32_t fb = full0 + s * 8;
            mbar_expect_tx(fb, STG3_BYTES);
            uint32_t a0 = tiles + s * STG3_BYTES;
            tma_load_3d(a0,                &tmAhi, s * 64, aY, aZ, fb);
            tma_load_3d(a0 + OP_BYTES,     &tmAlo, s * 64, aY, aZ, fb);
            tma_load_3d(a0 + 2 * OP_BYTES, &tmBhi, s * 64, n0, 0,  fb);
            tma_load_3d(a0 + 3 * OP_BYTES, &tmBlo, s * 64, n0, 0,  fb);
        }
    }

    float acc[4][4][4];
#pragma unroll
    for (int mi = 0; mi < 4; mi++)
#pragma unroll
        for (int ni = 0; ni < 4; ni++)
#pragma unroll
            for (int q = 0; q < 4; q++) acc[mi][ni][q] = 0.f;

    const int aR = lane & 15;
    const int aC = (lane >> 4) << 4;
    const int bR = ((lane >> 4) << 3) + (lane & 7);
    const int bC = ((lane >> 3) & 1) << 4;

    for (int kb = 0; kb < KB; kb++) {
        const int s = kb % ST3;
        const uint32_t ph = (uint32_t)((kb / ST3) & 1);
        mbar_wait(full0 + s * 8, ph);

        const uint32_t A0 = tiles + s * STG3_BYTES;
        const uint32_t B0 = A0 + 2 * OP_BYTES;

#pragma unroll
        for (int ki = 0; ki < 4; ki++) {
            const int kc = ki * 32;
            uint32_t ahi[4][4], alo[4][4], bhi[4][2], blo[4][2];
#pragma unroll
            for (int mi = 0; mi < 4; mi++) {
                int r = warp_row * 64 + mi * 16 + aR;
                uint32_t ad = swz(A0, r, kc + aC);
                ldsm4(ahi[mi], ad);
                ldsm4(alo[mi], ad + OP_BYTES);
            }
#pragma unroll
            for (int g = 0; g < 2; g++) {
                int r = warp_col * 32 + g * 16 + bR;
                uint32_t bd = swz(B0, r, kc + bC);
                uint32_t tr[4];
                ldsm4(tr, bd);
                bhi[2 * g][0] = tr[0]; bhi[2 * g][1] = tr[1];
                bhi[2 * g + 1][0] = tr[2]; bhi[2 * g + 1][1] = tr[3];
                ldsm4(tr, bd + OP_BYTES);
                blo[2 * g][0] = tr[0]; blo[2 * g][1] = tr[1];
                blo[2 * g + 1][0] = tr[2]; blo[2 * g + 1][1] = tr[3];
            }
#pragma unroll
            for (int mi = 0; mi < 4; mi++)
#pragma unroll
                for (int ni = 0; ni < 4; ni++) {
                    mma_f16(acc[mi][ni], ahi[mi], bhi[ni]);
                    mma_f16(acc[mi][ni], ahi[mi], blo[ni]);
                    mma_f16(acc[mi][ni], alo[mi], bhi[ni]);
                }
        }

        mbar_arrive(empty0 + s * 8);

        if (tid == 0 && kb + ST3 < KB) {
            mbar_wait(empty0 + s * 8, ph);
            uint32_t fb = full0 + s * 8;
            mbar_expect_tx(fb, STG3_BYTES);
            uint32_t a0 = tiles + s * STG3_BYTES;
            int kx = (kb + ST3) * 64;
            tma_load_3d(a0,                &tmAhi, kx, aY, aZ, fb);
            tma_load_3d(a0 + OP_BYTES,     &tmAlo, kx, aY, aZ, fb);
            tma_load_3d(a0 + 2 * OP_BYTES, &tmBhi, kx, n0, 0,  fb);
            tma_load_3d(a0 + 3 * OP_BYTES, &tmBlo, kx, n0, 0,  fb);
        }
    }

#pragma unroll
    for (int mi = 0; mi < 4; mi++) {
        int r = m0 + warp_row * 64 + mi * 16 + (lane >> 2);
#pragma unroll
        for (int ni = 0; ni < 4; ni++) {
            int cc = n0 + warp_col * 32 + ni * 8 + (lane & 3) * 2;
            *(__half2*)(Cout + (size_t)r * 1024 + cc) =
                __half2(__float2half_rn(acc[mi][ni][0]),
                        __float2half_rn(acc[mi][ni][1]));
            *(__half2*)(Cout + (size_t)(r + 8) * 1024 + cc) =
                __half2(__float2half_rn(acc[mi][ni][2]),
                        __float2half_rn(acc[mi][ni][3]));
        }
    }
}

// ---------------------------------------------------------------------------
__global__ __launch_bounds__(256) void cvt_all_kernel(
    const float* __restrict__ key, __half* __restrict__ dk,
    const float* __restrict__ value, __half* __restrict__ dv,
    const float* __restrict__ Wk, __half* __restrict__ dwk,
    const float* __restrict__ Wv, __half* __restrict__ dwv)
{
    int b = blockIdx.x;
    const float* s; __half* d; int i;
    if (b < 16384)      { s = key;   d = dk;  i = b; }
    else if (b < 32768) { s = value; d = dv;  i = b - 16384; }
    else if (b < 33280) { s = Wk;    d = dwk; i = b - 32768; }
    else                { s = Wv;    d = dwv; i = b - 33280; }
    int idx = (i * 256 + threadIdx.x) * 8;
    float4 v0 = *(const float4*)(s + idx);
    float4 v1 = *(const float4*)(s + idx + 4);
    __half2 h[4];
    h[0] = __floats2half2_rn(v0.x, v0.y);
    h[1] = __floats2half2_rn(v0.z, v0.w);
    h[2] = __floats2half2_rn(v1.x, v1.y);
    h[3] = __floats2half2_rn(v1.z, v1.w);
    *(uint4*)(d + idx) = *(uint4*)h;
}

__global__ __launch_bounds__(256) void cvt16_kernel(
    const float* __restrict__ src, __half* __restrict__ dst, int n)
{
    int i = (blockIdx.x * 256 + threadIdx.x) * 8;
    if (i >= n) return;
    float4 v0 = *(const float4*)(src + i);
    float4 v1 = *(const float4*)(src + i + 4);
    __half2 h[4];
    h[0] = __floats2half2_rn(v0.x, v0.y);
    h[1] = __floats2half2_rn(v0.z, v0.w);
    h[2] = __floats2half2_rn(v1.x, v1.y);
    h[3] = __floats2half2_rn(v1.z, v1.w);
    *(uint4*)(dst + i) = *(uint4*)h;
}

__global__ __launch_bounds__(256) void tsplit16_kernel(
    const float* __restrict__ W, __half* __restrict__ hi, __half* __restrict__ lo)
{
    __shared__ float t[32][33];
    const int o0 = blockIdx.y * 32, i0 = blockIdx.x * 32;
    const int c = threadIdx.x & 31;
    const int r0 = threadIdx.x >> 5;
#pragma unroll
    for (int it = 0; it < 4; it++) {
        int r = r0 + it * 8;
        t[r][c] = W[(size_t)(o0 + r) * 1024 + i0 + c];
    }
    __syncthreads();
#pragma unroll
    for (int it = 0; it < 4; it++) {
        int r = r0 + it * 8;
        float v = t[c][r];
        __half h = __float2half_rn(v);
        size_t idx = (size_t)(i0 + r) * 1024 + o0 + c;
        hi[idx] = h;
        lo[idx] = __float2half_rn(v - __half2float(h));
    }
}

// ---------------------------------------------------------------------------
// p_attn core + edges fused. grid (32 bh, 16 s-split), block 256.
// ---------------------------------------------------------------------------
__global__ __launch_bounds__(256) void pa_core_mma(
    const __half* __restrict__ k16, const __half* __restrict__ vh16,
    const float* __restrict__ pos, float* __restrict__ pa)
{
    __shared__ __half Ks[32 * 136];
    __shared__ __half Vh[32 * 136];
    __shared__ float ps[32];

    const int bh = blockIdx.x;
    const int b = bh >> 3;
    const int sp = blockIdx.y;
    const int tid = threadIdx.x;
    const int wid = tid >> 5, lane = tid & 31;
    const int warp_row = wid >> 2;
    const int warp_col = wid & 3;

    const uint32_t ksb = smem_u32(Ks);
    const uint32_t vhb = smem_u32(Vh);

    const size_t gbase = ((size_t)bh * NS + sp * 512) * NDK;
    const float* posb = pos + (size_t)b * NS + sp * 512;

    float acc[4][4][4];
#pragma unroll
    for (int mi = 0; mi < 4; mi++)
#pragma unroll
        for (int ni = 0; ni < 4; ni++)
#pragma unroll
            for (int q = 0; q < 4; q++) acc[mi][ni][q] = 0.f;

    float eacc = 0.f;
    float p2 = 0.f;

    const int aRow = (lane & 7) | ((lane >> 4) << 3);
    const int aCol = ((lane >> 3) & 1) << 3;
    const int bRow = (lane & 7) | (((lane >> 3) & 1) << 3);
    const int bCol = ((lane >> 4) & 1) << 3;
    const int ecol = tid & 127;

    for (int s0 = 0; s0 < 512; s0 += 32) {
#pragma unroll
        for (int it = 0; it < 2; it++) {
            int f = tid + it * 256;
            int row = f >> 4;
            int c8 = (f & 15) * 8;
            size_t ga = gbase + (size_t)(s0 + row) * NDK + c8;
            int so = row * 136 + c8;
            *(float4*)(Ks + so) = *(const float4*)(k16 + ga);
            *(float4*)(Vh + so) = *(const float4*)(vh16 + ga);
        }
        if (tid < 32) ps[tid] = posb[s0 + tid];
        __syncthreads();

#pragma unroll
        for (int ki = 0; ki < 2; ki++) {
            const int kio = ki * 16;
            uint32_t af[4][4], bhi[4][2];
#pragma unroll
            for (int mi = 0; mi < 4; mi++) {
                int mcol = warp_row * 64 + mi * 16 + aCol;
                ldsm4t(af[mi], ksb + (kio + aRow) * 272 + mcol * 2);
            }
#pragma unroll
            for (int g = 0; g < 2; g++) {
                int ec = warp_col * 32 + g * 16 + bCol;
                uint32_t tr[4];
                ldsm4t(tr, vhb + (kio + bRow) * 272 + ec * 2);
                bhi[2 * g][0] = tr[0]; bhi[2 * g][1] = tr[1];
                bhi[2 * g + 1][0] = tr[2]; bhi[2 * g + 1][1] = tr[3];
            }
#pragma unroll
            for (int mi = 0; mi < 4; mi++)
#pragma unroll
                for (int ni = 0; ni < 4; ni++)
                    mma_f16(acc[mi][ni], af[mi], bhi[ni]);
        }

        if (tid < 128) {
#pragma unroll 8
            for (int r = 0; r < 32; r++)
                eacc = fmaf(ps[r], __half2float(Vh[r * 136 + ecol]), eacc);
        } else {
#pragma unroll 8
            for (int r = 0; r < 32; r++)
                eacc = fmaf(ps[r], __half2float(Ks[r * 136 + ecol]), eacc);
        }
        if (wid == 0) { float pv = ps[lane]; p2 = fmaf(pv, pv, p2); }
        __syncthreads();
    }

    const float invS = 1.0f / (float)NS;
    float* pab = pa + (size_t)bh * NE * NE;
#pragma unroll
    for (int mi = 0; mi < 4; mi++) {
        int d0 = warp_row * 64 + mi * 16 + (lane >> 2);
#pragma unroll
        for (int ni = 0; ni < 4; ni++) {
            int e0 = warp_col * 32 + ni * 8 + (lane & 3) * 2;
            atomicAdd(&pab[(1 + d0) * NE + 1 + e0],     acc[mi][ni][0] * invS);
            atomicAdd(&pab[(1 + d0) * NE + 2 + e0],     acc[mi][ni][1] * invS);
            atomicAdd(&pab[(1 + d0 + 8) * NE + 1 + e0], acc[mi][ni][2] * invS);
            atomicAdd(&pab[(1 + d0 + 8) * NE + 2 + e0], acc[mi][ni][3] * invS);
        }
    }
    if (tid < 128) atomicAdd(&pab[0 * NE + 1 + ecol], eacc * invS);
    else           atomicAdd(&pab[(1 + ecol) * NE + 0], eacc * invS);
    if (wid == 0) {
#pragma unroll
        for (int o = 16; o > 0; o >>= 1)
            p2 += __shfl_xor_sync(0xffffffffu, p2, o);
        if (lane == 0) atomicAdd(&pab[0], p2 * invS);
    }
}

// ---------------------------------------------------------------------------
// Gd (fp16 hi/lo) = pa @ Wfc_h^T; outer-product, 64-wide n tiles (2 CTAs/SM).
// grid (16 ntile64, 8 h, 4 b), 256 threads as 16x16; 2 d-passes.
// ---------------------------------------------------------------------------
__global__ __launch_bounds__(256) void g_kernel(
    const float* __restrict__ pa, const float* __restrict__ Wfc,
    __half* __restrict__ gdh, __half* __restrict__ gdl, float* __restrict__ gpos)
{
    extern __shared__ float sm[];
    float* pat = sm;                  // [129 e][132 d-stride]
    float* wt  = sm + 129 * 132;      // [129 e][68 n-stride]

    const int nt = blockIdx.x, h = blockIdx.y, b = blockIdx.z;
    const int tid = threadIdx.x;
    const int n0 = nt * 64;
    const int ty = tid >> 4, tx = tid & 15;

    const float* pab = pa + ((size_t)(b * NH + h)) * NE * NE;
    for (int i = tid; i < NE * NE; i += 256) {
        int d = i / NE, e = i - d * NE;
        pat[e * 132 + d] = pab[i];
    }
    for (int i = tid; i < 64 * NE; i += 256) {
        int n = i / NE, e = i - n * NE;
        wt[e * 68 + n] = Wfc[(size_t)(n0 + n) * KFC + h * NE + e];
    }
    __syncthreads();

    const int nn = ty * 4;   // 16 * 4 = 64 n covered
#pragma unroll
    for (int pd = 0; pd < 2; pd++) {
        const int dd = pd * 64 + tx * 4;
        float acc[4][4];
#pragma unroll
        for (int i = 0; i < 4; i++)
#pragma unroll
            for (int j = 0; j < 4; j++) acc[i][j] = 0.f;

        for (int e = 0; e < NE; e++) {
            float4 a = *(const float4*)(wt + e * 68 + nn);
            float4 p = *(const float4*)(pat + e * 132 + dd);
            float ar[4] = {a.x, a.y, a.z, a.w};
            float pr[4] = {p.x, p.y, p.z, p.w};
#pragma unroll
            for (int i = 0; i < 4; i++)
#pragma unroll
                for (int j = 0; j < 4; j++)
                    acc[i][j] = fmaf(ar[i], pr[j], acc[i][j]);
        }

#pragma unroll
        for (int i = 0; i < 4; i++) {
            int n = nn + i;
#pragma unroll
            for (int j = 0; j < 4; j++) {
                int d = dd + j;
                float v = acc[i][j];
                if (d == 0) {
                    atomicAdd(&gpos[b * 1024 + n0 + n], v);
                } else {
                    size_t idx = ((size_t)b * 1024 + n0 + n) * 1024
                                 + h * NDK + d - 1;
                    __half hh = __float2half_rn(v);
                    gdh[idx] = hh;
                    gdl[idx] = __float2half_rn(v - __half2float(hh));
                }
            }
        }
    }

    // d = 128 column (last of 129)
    if (tid < 64) {
        int n = tid;
        float accv = 0.f;
        for (int e = 0; e < NE; e++)
            accv = fmaf(wt[e * 68 + n], pat[e * 132 + 128], accv);
        size_t idx = ((size_t)b * 1024 + n0 + n) * 1024 + h * NDK + 127;
        __half hh = __float2half_rn(accv);
        gdh[idx] = hh;
        gdl[idx] = __float2half_rn(accv - __half2float(hh));
    }
}

// ---------------------------------------------------------------------------
__global__ __launch_bounds__(256) void bias2_kernel(
    const __half* __restrict__ gdh, const __half* __restrict__ gdl,
    const float* __restrict__ bq, const float* __restrict__ bfc,
    float* __restrict__ bias2)
{
    const int n = blockIdx.x, b = blockIdx.y;
    const int tid = threadIdx.x;
    size_t base = ((size_t)b * 1024 + n) * 1024;
    float acc = 0.f;
    for (int o = tid; o < 1024; o += 256) {
        float v = __half2float(gdh[base + o]) + __half2float(gdl[base + o]);
        acc = fmaf(bq[o], v, acc);
    }
    __shared__ float red[256];
    red[tid] = acc;
    __syncthreads();
    for (int o = 128; o > 0; o >>= 1) {
        if (tid < o) red[tid] += red[tid + o];
        __syncthreads();
    }
    if (tid == 0) bias2[b * 1024 + n] = red[0] + bfc[n];
}

// ============================ host side ====================================
typedef CUresult (*EncodeFn)(CUtensorMap*, CUtensorMapDataType, cuuint32_t, void*,
                             const cuuint64_t*, const cuuint64_t*, const cuuint32_t*,
                             const cuuint32_t*, CUtensorMapInterleave, CUtensorMapSwizzle,
                             CUtensorMapL2promotion, CUtensorMapFloatOOBfill);

static EncodeFn get_encode() {
    static EncodeFn fn = nullptr;
    if (!fn) {
        void* p = nullptr;
        cudaDriverEntryPointQueryResult st;
        cudaGetDriverEntryPoint("cuTensorMapEncodeTiled", &p, cudaEnableDefault, &st);
        fn = (EncodeFn)p;
    }
    return fn;
}

static void encode_f16(CUtensorMap* m, const void* base,
                       uint64_t kdim, uint64_t rows, uint64_t nz, uint32_t boxRows) {
    cuuint64_t dims[3]    = { kdim, rows, nz };
    cuuint64_t strides[2] = { kdim * 2, rows * kdim * 2 };
    cuuint32_t box[3]     = { 64, boxRows, 1 };
    cuuint32_t est[3]     = { 1, 1, 1 };
    get_encode()(m, CU_TENSOR_MAP_DATA_TYPE_FLOAT16, 3, (void*)base,
                 dims, strides, box, est,
                 CU_TENSOR_MAP_INTERLEAVE_NONE, CU_TENSOR_MAP_SWIZZLE_128B,
                 CU_TENSOR_MAP_L2_PROMOTION_L2_128B, CU_TENSOR_MAP_FLOAT_OOB_FILL_NONE);
}

extern "C" void kernel_launch(void* const* d_in, const int* in_sizes, int n_in,
                              void* d_out, int out_size)
{
    (void)in_sizes; (void)n_in; (void)out_size;
    const float* query = (const float*)d_in[0];
    const float* key   = (const float*)d_in[1];
    const float* value = (const float*)d_in[2];
    const float* pos   = (const float*)d_in[3];
    const float* Wq    = (const float*)d_in[4];
    const float* bq    = (const float*)d_in[5];
    const float* Wk    = (const float*)d_in[6];
    const float* bk    = (const float*)d_in[7];
    const float* Wv    = (const float*)d_in[8];
    const float* bv    = (const float*)d_in[9];
    const float* gK    = (const float*)d_in[10];
    const float* betaK = (const float*)d_in[11];
    const float* gV    = (const float*)d_in[12];
    const float* betaV = (const float*)d_in[13];
    const float* Wfc   = (const float*)d_in[14];
    const float* bfc   = (const float*)d_in[15];
    float* out = (float*)d_out;

    float *pa, *gpos, *bias2;
    __half *a16, *c16, *bh16, *bl16, *k16, *vh16, *wc16;
    cudaGetSymbolAddress((void**)&pa, g_pa);
    cudaGetSymbolAddress((void**)&gpos, g_gpos);
    cudaGetSymbolAddress((void**)&bias2, g_bias2);
    cudaGetSymbolAddress((void**)&a16, g_a16);
    cudaGetSymbolAddress((void**)&c16, g_c16);
    cudaGetSymbolAddress((void**)&bh16, g_bh16);
    cudaGetSymbolAddress((void**)&bl16, g_bl16);
    cudaGetSymbolAddress((void**)&k16, g_k16);
    cudaGetSymbolAddress((void**)&vh16, g_vh16);
    cudaGetSymbolAddress((void**)&wc16, g_wc16);

    cudaFuncSetAttribute(gemm_kv, cudaFuncAttributeMaxDynamicSharedMemorySize,
                         (int)SMEM_KV);
    cudaFuncSetAttribute(gemm_out, cudaFuncAttributeMaxDynamicSharedMemorySize,
                         (int)SMEM_OUT);
    cudaFuncSetAttribute(gemm_mma3, cudaFuncAttributeMaxDynamicSharedMemorySize,
                         (int)SMEM3_DYN);
    cudaFuncSetAttribute(g_kernel, cudaFuncAttributeMaxDynamicSharedMemorySize,
                         (int)SMEM_G);

    CUtensorMap tAK, tAV, tBkv, tGh, tGl, tWqh, tWql, tAq, tWc;
    encode_f16(&tAK, a16, 1024, 32768, 1, 128);
    encode_f16(&tAV, c16, 1024, 32768, 1, 128);
    encode_f16(&tBkv, bh16, 1024, 1024, 2, 256);
    encode_f16(&tGh,  a16,           1024, 1024, 4, 128);
    encode_f16(&tGl,  a16 + 4194304, 1024, 1024, 4, 128);
    encode_f16(&tWqh, bh16, 1024, 1024, 1, 128);
    encode_f16(&tWql, bl16, 1024, 1024, 1, 128);
    encode_f16(&tAq,  a16,  1024, 32768, 1, 128);
    encode_f16(&tWc,  wc16, 1024, 1024, 4, 256);

    const int NA = 33554432, NW = 1048576;

    // Inputs to fp16 (key, value, Wk, Wv in one launch)
    cvt_all_kernel<<<33792, 256>>>(key, a16, value, c16,
                                   Wk, bh16, Wv, bh16 + NW);

    // K+V projection with fused per-head LN (BN=256: 2 heads per tile)
    gemm_kv<<<dim3(4, 256, 2), 288, SMEM_KV>>>(
        tAK, tAV, tBkv, bk, bv, gK, betaK, gV, betaV, k16, vh16);

    // p_attn = Kc^T Vc / S  (core + edges fused)
    cudaMemsetAsync(pa, 0, (size_t)32 * NE * NE * sizeof(float));
    pa_core_mma<<<dim3(32, 16), 256>>>(k16, vh16, pos, pa);

    // Gd (fp16 hi/lo directly into a16) + gpos  (64-wide n tiles, 2 CTAs/SM)
    cudaMemsetAsync(gpos, 0, 4096 * sizeof(float));
    g_kernel<<<dim3(16, NH, NB), 256, SMEM_G>>>(
        pa, Wfc, a16, a16 + 4194304, gpos);

    // bias2 = bfc + bq @ (Gd hi+lo)^T
    bias2_kernel<<<dim3(1024, 4), 256>>>(a16, a16 + 4194304, bq, bfc, bias2);

    // Wq^T hi/lo
    tsplit16_kernel<<<dim3(32, 32), 256>>>(Wq, bh16, bl16);

    // Wcomb[b] = Gd[b] @ Wq (3-pass) -> fp16 directly into wc16
    gemm_mma3<<<dim3(8, 8, 4), 256, SMEM3_DYN>>>(tGh, tGl, tWqh, tWql, wc16, 16);

    // query -> fp16 (a16 free after gemm_mma3 consumed Gd)
    cvt16_kernel<<<NA / 2048, 256>>>(query, a16, NA);

    // out[b] = query[b] @ Wcomb[b]^T + pos (x) gpos[b] + bias2[b]  (BN=256)
    gemm_out<<<dim3(4, 64, 4), 288, SMEM_OUT>>>(tAq, tWc, bias2, pos, gpos, out);
}

// round 15
// speedup vs baseline: 1.4466x; 1.4466x over previous
#include <cuda_runtime.h>
#include <cuda.h>
#include <cuda_fp16.h>
#include <cstdint>
#include <cstddef>

// Problem constants
#define NB 4
#define NS 8192
#define ND 1024
#define NH 8
#define NDK 128
#define NE 129
#define NM 32768
#define KFC 1032

// ---------------- scratch (static device globals; no allocations) ----------
static __device__ float g_pa[532512];       // (32, 129, 129) p_attn
static __device__ float g_gpos[4096];       // (B, 1024) pos-column of G (sum over h)
static __device__ float g_bias2[4096];      // (B, 1024) folded bias
static __device__ __half g_a16[33554432];   // key fp16 / Gd hi+lo / query fp16
static __device__ __half g_c16[33554432];   // value fp16
static __device__ __half g_bh16[4227072];   // B hi (Wk+Wv / Wq hi)
static __device__ __half g_bl16[4227072];   // B lo (Wq lo for gemm3)
static __device__ __half g_k16[33554432];   // LN'd K, head-major (bh,s,d) fp16
static __device__ __half g_vh16[33554432];  // LN'd V, head-major fp16
static __device__ __half g_wc16[4194304];   // Wcomb fp16 (B,1024,1024)

// ============================ PTX helpers ==================================
__device__ __forceinline__ uint32_t smem_u32(const void* p) {
    uint32_t a;
    asm("{ .reg .u64 t; cvta.to.shared.u64 t, %1; cvt.u32.u64 %0, t; }"
        : "=r"(a) : "l"(p));
    return a;
}
__device__ __forceinline__ void mbar_init(uint32_t mbar, uint32_t cnt) {
    asm volatile("mbarrier.init.shared.b64 [%0], %1;" :: "r"(mbar), "r"(cnt) : "memory");
}
__device__ __forceinline__ void mbar_expect_tx(uint32_t mbar, uint32_t bytes) {
    asm volatile("mbarrier.arrive.expect_tx.shared.b64 _, [%0], %1;"
                 :: "r"(mbar), "r"(bytes) : "memory");
}
__device__ __forceinline__ void mbar_arrive(uint32_t mbar) {
    asm volatile("mbarrier.arrive.shared.b64 _, [%0];" :: "r"(mbar) : "memory");
}
__device__ __forceinline__ void mbar_wait(uint32_t mbar, uint32_t parity) {
    asm volatile(
        "{\n\t.reg .pred P;\n\t"
        "BWL_%=:\n\t"
        "mbarrier.try_wait.parity.acquire.cta.shared::cta.b64 P, [%0], %1, 0x989680;\n\t"
        "@P bra.uni BWD_%=;\n\t"
        "bra.uni BWL_%=;\n\t"
        "BWD_%=:\n\t}"
        :: "r"(mbar), "r"(parity) : "memory");
}
__device__ __forceinline__ void tma_load_3d(uint32_t dst, const CUtensorMap* tm,
                                            int x, int y, int z, uint32_t mbar) {
    asm volatile(
        "cp.async.bulk.tensor.3d.shared::cta.global.tile.mbarrier::complete_tx::bytes "
        "[%0], [%1, {%2, %3, %4}], [%5];"
        :: "r"(dst), "l"(tm), "r"(x), "r"(y), "r"(z), "r"(mbar) : "memory");
}
__device__ __forceinline__ void fence_async_shared() {
    asm volatile("fence.proxy.async.shared::cta;" ::: "memory");
}
__device__ __forceinline__ void ldsm4(uint32_t* r, uint32_t addr) {
    asm volatile("ldmatrix.sync.aligned.m8n8.x4.shared.b16 {%0,%1,%2,%3}, [%4];"
                 : "=r"(r[0]), "=r"(r[1]), "=r"(r[2]), "=r"(r[3]) : "r"(addr));
}
__device__ __forceinline__ void ldsm4t(uint32_t* r, uint32_t addr) {
    asm volatile("ldmatrix.sync.aligned.m8n8.x4.trans.shared.b16 {%0,%1,%2,%3}, [%4];"
                 : "=r"(r[0]), "=r"(r[1]), "=r"(r[2]), "=r"(r[3]) : "r"(addr));
}
__device__ __forceinline__ void mma_f16(float* c, const uint32_t* a, const uint32_t* b) {
    asm volatile(
        "mma.sync.aligned.m16n8k16.row.col.f32.f16.f16.f32 "
        "{%0,%1,%2,%3}, {%4,%5,%6,%7}, {%8,%9}, {%0,%1,%2,%3};"
        : "+f"(c[0]), "+f"(c[1]), "+f"(c[2]), "+f"(c[3])
        : "r"(a[0]), "r"(a[1]), "r"(a[2]), "r"(a[3]), "r"(b[0]), "r"(b[1]));
}
__device__ __forceinline__ uint32_t swz(uint32_t base, int r, int c) {
    return base + r * 128 + (c ^ ((r & 7) << 4));
}

// ============================ GEMM constants ===============================
static constexpr uint32_t OPA_BYTES = 128 * 64 * 2;   // 16 KB
static constexpr uint32_t OPB_BYTES = 256 * 64 * 2;   // 32 KB
static constexpr uint32_t STG_BYTES = OPA_BYTES + OPB_BYTES;  // 48 KB
static constexpr uint32_t CTRL_BYTES = 1024;
static constexpr int ST = 4;
static constexpr uint32_t STAGES_END = CTRL_BYTES + ST * STG_BYTES;   // 197632
static constexpr uint32_t SMEM_KV = STAGES_END + 16384 + 2048;        // 216064
static constexpr uint32_t SMEM_OUT = STAGES_END;                      // 197632

// ============================ K/V projection + fused LN ====================
// grid (4 nblk, 256 m-tiles, 2 kv), 288 threads (8 compute + producer warp).
__global__ __launch_bounds__(288, 1) void gemm_kv(
    const __grid_constant__ CUtensorMap tmAK,
    const __grid_constant__ CUtensorMap tmAV,
    const __grid_constant__ CUtensorMap tmB,    // batched (z: 0=Wk, 1=Wv)
    const float* __restrict__ bk, const float* __restrict__ bv,
    const float* __restrict__ gK, const float* __restrict__ betaK,
    const float* __restrict__ gV, const float* __restrict__ betaV,
    __half* __restrict__ k16, __half* __restrict__ vh16)
{
    extern __shared__ __align__(1024) char smem[];
    const uint32_t sb = smem_u32(smem);
    const int tid = threadIdx.x;
    const int wid = tid >> 5, lane = tid & 31;
    const int warp_row = wid >> 2;
    const int warp_col = wid & 3;
    const bool producer = (wid == 8);

    const uint32_t full0  = sb;
    const uint32_t empty0 = sb + 128;
    const uint32_t tiles  = sb + CTRL_BYTES;

    const int nblk = blockIdx.x;
    const int n0g = nblk * 256;
    const int m0 = blockIdx.y * 128;
    const int zKV = blockIdx.z;
    const CUtensorMap* tmA = zKV ? &tmAV : &tmAK;
    const int KB = 16;

    if (tid == 0) {
        for (int s = 0; s < ST; s++) {
            mbar_init(full0 + s * 8, 1);
            mbar_init(empty0 + s * 8, 256);
        }
        fence_async_shared();
    }
    __syncthreads();

    float acc[4][8][4];
#pragma unroll
    for (int mi = 0; mi < 4; mi++)
#pragma unroll
        for (int ni = 0; ni < 8; ni++)
#pragma unroll
            for (int q = 0; q < 4; q++) acc[mi][ni][q] = 0.f;

    if (producer) {
        if (lane == 0) {
            for (int s = 0; s < ST; s++) {
                uint32_t fb = full0 + s * 8;
                mbar_expect_tx(fb, STG_BYTES);
                uint32_t a0 = tiles + s * STG_BYTES;
                tma_load_3d(a0,             tmA,  s * 64, m0,  0,   fb);
                tma_load_3d(a0 + OPA_BYTES, &tmB, s * 64, n0g, zKV, fb);
            }
            for (int kb = ST; kb < KB; kb++) {
                int s = kb % ST;
                mbar_wait(empty0 + s * 8, (uint32_t)(((kb - ST) / ST) & 1));
                uint32_t fb = full0 + s * 8;
                mbar_expect_tx(fb, STG_BYTES);
                uint32_t a0 = tiles + s * STG_BYTES;
                tma_load_3d(a0,             tmA,  kb * 64, m0,  0,   fb);
                tma_load_3d(a0 + OPA_BYTES, &tmB, kb * 64, n0g, zKV, fb);
            }
        }
    } else {
        const int aR = lane & 15;
        const int aC = (lane >> 4) << 4;
        const int bR = ((lane >> 4) << 3) + (lane & 7);
        const int bC = ((lane >> 3) & 1) << 4;

        for (int kb = 0; kb < KB; kb++) {
            const int s = kb % ST;
            mbar_wait(full0 + s * 8, (uint32_t)((kb / ST) & 1));

            const uint32_t A0 = tiles + s * STG_BYTES;
            const uint32_t B0 = A0 + OPA_BYTES;

#pragma unroll
            for (int ki = 0; ki < 4; ki++) {
                const int kc = ki * 32;
                uint32_t af[4][4], bhi[8][2];
#pragma unroll
                for (int mi = 0; mi < 4; mi++) {
                    int r = warp_row * 64 + mi * 16 + aR;
                    ldsm4(af[mi], swz(A0, r, kc + aC));
                }
#pragma unroll
                for (int g = 0; g < 4; g++) {
                    int r = warp_col * 64 + g * 16 + bR;
                    uint32_t tr[4];
                    ldsm4(tr, swz(B0, r, kc + bC));
                    bhi[2 * g][0] = tr[0]; bhi[2 * g][1] = tr[1];
                    bhi[2 * g + 1][0] = tr[2]; bhi[2 * g + 1][1] = tr[3];
                }
                if (ki == 3) mbar_arrive(empty0 + s * 8);
#pragma unroll
                for (int mi = 0; mi < 4; mi++)
#pragma unroll
                    for (int ni = 0; ni < 8; ni++)
                        mma_f16(acc[mi][ni], af[mi], bhi[ni]);
            }
        }
    }

    // ---- fused LN epilogue ----
    __syncthreads();

    float2* part  = (float2*)(smem + STAGES_END);           // [128][16]
    float2* stats = (float2*)(smem + STAGES_END + 16384);   // [128][2]

    const float* biasp = zKV ? bv : bk;
    const float* gsel  = zKV ? gV : gK;
    const float* besel = zKV ? betaV : betaK;
    __half* outp = zKV ? vh16 : k16;
    const int hh = warp_col >> 1;

    if (!producer) {
        const int slot = warp_col * 4 + (lane & 3);
#pragma unroll
        for (int mi = 0; mi < 4; mi++) {
#pragma unroll
            for (int ni = 0; ni < 8; ni++) {
                int col = warp_col * 64 + ni * 8 + (lane & 3) * 2;
                float b0v = biasp[n0g + col], b1v = biasp[n0g + col + 1];
                acc[mi][ni][0] += b0v; acc[mi][ni][1] += b1v;
                acc[mi][ni][2] += b0v; acc[mi][ni][3] += b1v;
            }
#pragma unroll
            for (int half = 0; half < 2; half++) {
                float s = 0.f, sq = 0.f;
#pragma unroll
                for (int ni = 0; ni < 8; ni++) {
                    float v0 = acc[mi][ni][half * 2 + 0];
                    float v1 = acc[mi][ni][half * 2 + 1];
                    s += v0 + v1;
                    sq += v0 * v0 + v1 * v1;
                }
                int r = warp_row * 64 + mi * 16 + (lane >> 2) + half * 8;
                part[r * 16 + slot] = make_float2(s, sq);
            }
        }
    }
    __syncthreads();
    if (tid < 256) {
        int r = tid >> 1, hsel = tid & 1;
        float s = 0.f, sq = 0.f;
#pragma unroll
        for (int i = 0; i < 8; i++) {
            float2 p = part[r * 16 + hsel * 8 + i];
            s += p.x; sq += p.y;
        }
        float mean = s * (1.f / 128.f);
        float var  = sq * (1.f / 128.f) - mean * mean;
        stats[r * 2 + hsel] = make_float2(mean, rsqrtf(var + 1e-5f));
    }
    __syncthreads();

    if (!producer) {
#pragma unroll
        for (int mi = 0; mi < 4; mi++) {
#pragma unroll
            for (int half = 0; half < 2; half++) {
                int r = warp_row * 64 + mi * 16 + (lane >> 2) + half * 8;
                float2 st = stats[r * 2 + hh];
                int m = m0 + r;
                int b = m >> 13, sIdx = m & 8191;
                size_t base = (((size_t)(b * NH + nblk * 2 + hh)) * NS + sIdx) * NDK;
#pragma unroll
                for (int ni = 0; ni < 8; ni++) {
                    int col = warp_col * 64 + ni * 8 + (lane & 3) * 2;
                    int c128 = col & 127;
                    float gg0 = gsel[n0g + col],  gg1 = gsel[n0g + col + 1];
                    float be0 = besel[n0g + col], be1 = besel[n0g + col + 1];
                    float y0 = (acc[mi][ni][half * 2 + 0] - st.x) * st.y * gg0 + be0;
                    float y1 = (acc[mi][ni][half * 2 + 1] - st.x) * st.y * gg1 + be1;
                    *(__half2*)(outp + base + c128) =
                        __half2(__float2half_rn(y0), __float2half_rn(y1));
                }
            }
        }
    }
}

// ============================ final GEMM (BN=256) ==========================
__global__ __launch_bounds__(288, 1) void gemm_out(
    const __grid_constant__ CUtensorMap tmA,
    const __grid_constant__ CUtensorMap tmB,
    const float* __restrict__ bias2,
    const float* __restrict__ posv,
    const float* __restrict__ gposv,
    float* __restrict__ C)
{
    extern __shared__ __align__(1024) char smem[];
    const uint32_t sb = smem_u32(smem);
    const int tid = threadIdx.x;
    const int wid = tid >> 5, lane = tid & 31;
    const int warp_row = wid >> 2;
    const int warp_col = wid & 3;
    const bool producer = (wid == 8);

    const uint32_t full0  = sb;
    const uint32_t empty0 = sb + 128;
    const uint32_t tiles  = sb + CTRL_BYTES;

    const int n0 = blockIdx.x * 256;
    const int zB = blockIdx.z;
    const int m0 = zB * 8192 + blockIdx.y * 128;
    const int KB = 16;

    if (tid == 0) {
        for (int s = 0; s < ST; s++) {
            mbar_init(full0 + s * 8, 1);
            mbar_init(empty0 + s * 8, 256);
        }
        fence_async_shared();
    }
    __syncthreads();

    if (producer) {
        if (lane == 0) {
            for (int s = 0; s < ST; s++) {
                uint32_t fb = full0 + s * 8;
                mbar_expect_tx(fb, STG_BYTES);
                uint32_t a0 = tiles + s * STG_BYTES;
                tma_load_3d(a0,             &tmA, s * 64, m0, 0,  fb);
                tma_load_3d(a0 + OPA_BYTES, &tmB, s * 64, n0, zB, fb);
            }
            for (int kb = ST; kb < KB; kb++) {
                int s = kb % ST;
                mbar_wait(empty0 + s * 8, (uint32_t)(((kb - ST) / ST) & 1));
                uint32_t fb = full0 + s * 8;
                mbar_expect_tx(fb, STG_BYTES);
                uint32_t a0 = tiles + s * STG_BYTES;
                tma_load_3d(a0,             &tmA, kb * 64, m0, 0,  fb);
                tma_load_3d(a0 + OPA_BYTES, &tmB, kb * 64, n0, zB, fb);
            }
        }
        return;
    }

    float acc[4][8][4];
#pragma unroll
    for (int mi = 0; mi < 4; mi++)
#pragma unroll
        for (int ni = 0; ni < 8; ni++)
#pragma unroll
            for (int q = 0; q < 4; q++) acc[mi][ni][q] = 0.f;

    const int aR = lane & 15;
    const int aC = (lane >> 4) << 4;
    const int bR = ((lane >> 4) << 3) + (lane & 7);
    const int bC = ((lane >> 3) & 1) << 4;

    for (int kb = 0; kb < KB; kb++) {
        const int s = kb % ST;
        mbar_wait(full0 + s * 8, (uint32_t)((kb / ST) & 1));

        const uint32_t A0 = tiles + s * STG_BYTES;
        const uint32_t B0 = A0 + OPA_BYTES;

#pragma unroll
        for (int ki = 0; ki < 4; ki++) {
            const int kc = ki * 32;
            uint32_t af[4][4], bhi[8][2];
#pragma unroll
            for (int mi = 0; mi < 4; mi++) {
                int r = warp_row * 64 + mi * 16 + aR;
                ldsm4(af[mi], swz(A0, r, kc + aC));
            }
#pragma unroll
            for (int g = 0; g < 4; g++) {
                int r = warp_col * 64 + g * 16 + bR;
                uint32_t tr[4];
                ldsm4(tr, swz(B0, r, kc + bC));
                bhi[2 * g][0] = tr[0]; bhi[2 * g][1] = tr[1];
                bhi[2 * g + 1][0] = tr[2]; bhi[2 * g + 1][1] = tr[3];
            }
            if (ki == 3) mbar_arrive(empty0 + s * 8);
#pragma unroll
            for (int mi = 0; mi < 4; mi++)
#pragma unroll
                for (int ni = 0; ni < 8; ni++)
                    mma_f16(acc[mi][ni], af[mi], bhi[ni]);
        }
    }

    const float* biasp = bias2 + zB * 1024;
    const float* gpp   = gposv + zB * 1024;

#pragma unroll
    for (int mi = 0; mi < 4; mi++) {
        int r = m0 + warp_row * 64 + mi * 16 + (lane >> 2);
        float pv = posv[r];
        float pv2 = posv[r + 8];
#pragma unroll
        for (int ni = 0; ni < 8; ni++) {
            int cc = n0 + warp_col * 64 + ni * 8 + (lane & 3) * 2;
            float b0v = biasp[cc], b1v = biasp[cc + 1];
            float g0 = gpp[cc], g1 = gpp[cc + 1];
            float2 v0 = { acc[mi][ni][0] + b0v + pv * g0,
                          acc[mi][ni][1] + b1v + pv * g1 };
            float2 v1 = { acc[mi][ni][2] + b0v + pv2 * g0,
                          acc[mi][ni][3] + b1v + pv2 * g1 };
            *(float2*)(C + (size_t)r * 1024 + cc) = v0;
            *(float2*)(C + (size_t)(r + 8) * 1024 + cc) = v1;
        }
    }
}

// ============================ 3-pass GEMM (A hi/lo, B hi/lo) ===============
static constexpr int ST3 = 3;
static constexpr uint32_t OP_BYTES = 128 * 64 * 2;
static constexpr uint32_t STG3_BYTES = 4 * OP_BYTES;
static constexpr uint32_t SMEM3_DYN = CTRL_BYTES + ST3 * STG3_BYTES;

__global__ __launch_bounds__(256, 1) void gemm_mma3(
    const __grid_constant__ CUtensorMap tmAhi,
    const __grid_constant__ CUtensorMap tmAlo,
    const __grid_constant__ CUtensorMap tmBhi,
    const __grid_constant__ CUtensorMap tmBlo,
    __half* __restrict__ Cout, int KB)
{
    extern __shared__ __align__(1024) char smem[];
    const uint32_t sb = smem_u32(smem);
    const int tid = threadIdx.x;
    const int wid = tid >> 5, lane = tid & 31;
    const int warp_row = wid >> 2;
    const int warp_col = wid & 3;

    const uint32_t full0  = sb;
    const uint32_t empty0 = sb + 128;
    const uint32_t tiles  = sb + CTRL_BYTES;

    const int n0 = blockIdx.x * 128;
    const int aY = blockIdx.y * 128;
    const int aZ = blockIdx.z;
    const int m0 = blockIdx.z * 1024 + aY;

    if (tid == 0) {
        for (int s = 0; s < ST3; s++) {
            mbar_init(full0 + s * 8, 1);
            mbar_init(empty0 + s * 8, 256);
        }
        fence_async_shared();
    }
    __syncthreads();

    if (tid == 0) {
        for (int s = 0; s < ST3; s++) {
            uint32_t fb = full0 + s * 8;
            mbar_expect_tx(fb, STG3_BYTES);
            uint32_t a0 = tiles + s * STG3_BYTES;
            tma_load_3d(a0,                &tmAhi, s * 64, aY, aZ, fb);
            tma_load_3d(a0 + OP_BYTES,     &tmAlo, s * 64, aY, aZ, fb);
            tma_load_3d(a0 + 2 * OP_BYTES, &tmBhi, s * 64, n0, 0,  fb);
            tma_load_3d(a0 + 3 * OP_BYTES, &tmBlo, s * 64, n0, 0,  fb);
        }
    }

    float acc[4][4][4];
#pragma unroll
    for (int mi = 0; mi < 4; mi++)
#pragma unroll
        for (int ni = 0; ni < 4; ni++)
#pragma unroll
            for (int q = 0; q < 4; q++) acc[mi][ni][q] = 0.f;

    const int aR = lane & 15;
    const int aC = (lane >> 4) << 4;
    const int bR = ((lane >> 4) << 3) + (lane & 7);
    const int bC = ((lane >> 3) & 1) << 4;

    for (int kb = 0; kb < KB; kb++) {
        const int s = kb % ST3;
        const uint32_t ph = (uint32_t)((kb / ST3) & 1);
        mbar_wait(full0 + s * 8, ph);

        const uint32_t A0 = tiles + s * STG3_BYTES;
        const uint32_t B0 = A0 + 2 * OP_BYTES;

#pragma unroll
        for (int ki = 0; ki < 4; ki++) {
            const int kc = ki * 32;
            uint32_t ahi[4][4], alo[4][4], bhi[4][2], blo[4][2];
#pragma unroll
            for (int mi = 0; mi < 4; mi++) {
                int r = warp_row * 64 + mi * 16 + aR;
                uint32_t ad = swz(A0, r, kc + aC);
                ldsm4(ahi[mi], ad);
                ldsm4(alo[mi], ad + OP_BYTES);
            }
#pragma unroll
            for (int g = 0; g < 2; g++) {
                int r = warp_col * 32 + g * 16 + bR;
                uint32_t bd = swz(B0, r, kc + bC);
                uint32_t tr[4];
                ldsm4(tr, bd);
                bhi[2 * g][0] = tr[0]; bhi[2 * g][1] = tr[1];
                bhi[2 * g + 1][0] = tr[2]; bhi[2 * g + 1][1] = tr[3];
                ldsm4(tr, bd + OP_BYTES);
                blo[2 * g][0] = tr[0]; blo[2 * g][1] = tr[1];
                blo[2 * g + 1][0] = tr[2]; blo[2 * g + 1][1] = tr[3];
            }
#pragma unroll
            for (int mi = 0; mi < 4; mi++)
#pragma unroll
                for (int ni = 0; ni < 4; ni++) {
                    mma_f16(acc[mi][ni], ahi[mi], bhi[ni]);
                    mma_f16(acc[mi][ni], ahi[mi], blo[ni]);
                    mma_f16(acc[mi][ni], alo[mi], bhi[ni]);
                }
        }

        mbar_arrive(empty0 + s * 8);

        if (tid == 0 && kb + ST3 < KB) {
            mbar_wait(empty0 + s * 8, ph);
            uint32_t fb = full0 + s * 8;
            mbar_expect_tx(fb, STG3_BYTES);
            uint32_t a0 = tiles + s * STG3_BYTES;
            int kx = (kb + ST3) * 64;
            tma_load_3d(a0,                &tmAhi, kx, aY, aZ, fb);
            tma_load_3d(a0 + OP_BYTES,     &tmAlo, kx, aY, aZ, fb);
            tma_load_3d(a0 + 2 * OP_BYTES, &tmBhi, kx, n0, 0,  fb);
            tma_load_3d(a0 + 3 * OP_BYTES, &tmBlo, kx, n0, 0,  fb);
        }
    }

#pragma unroll
    for (int mi = 0; mi < 4; mi++) {
        int r = m0 + warp_row * 64 + mi * 16 + (lane >> 2);
#pragma unroll
        for (int ni = 0; ni < 4; ni++) {
            int cc = n0 + warp_col * 32 + ni * 8 + (lane & 3) * 2;
            *(__half2*)(Cout + (size_t)r * 1024 + cc) =
                __half2(__float2half_rn(acc[mi][ni][0]),
                        __float2half_rn(acc[mi][ni][1]));
            *(__half2*)(Cout + (size_t)(r + 8) * 1024 + cc) =
                __half2(__float2half_rn(acc[mi][ni][2]),
                        __float2half_rn(acc[mi][ni][3]));
        }
    }
}

// ---------------------------------------------------------------------------
__global__ __launch_bounds__(256) void cvt_all_kernel(
    const float* __restrict__ key, __half* __restrict__ dk,
    const float* __restrict__ value, __half* __restrict__ dv,
    const float* __restrict__ Wk, __half* __restrict__ dwk,
    const float* __restrict__ Wv, __half* __restrict__ dwv)
{
    int b = blockIdx.x;
    const float* s; __half* d; int i;
    if (b < 16384)      { s = key;   d = dk;  i = b; }
    else if (b < 32768) { s = value; d = dv;  i = b - 16384; }
    else if (b < 33280) { s = Wk;    d = dwk; i = b - 32768; }
    else                { s = Wv;    d = dwv; i = b - 33280; }
    int idx = (i * 256 + threadIdx.x) * 8;
    float4 v0 = *(const float4*)(s + idx);
    float4 v1 = *(const float4*)(s + idx + 4);
    __half2 h[4];
    h[0] = __floats2half2_rn(v0.x, v0.y);
    h[1] = __floats2half2_rn(v0.z, v0.w);
    h[2] = __floats2half2_rn(v1.x, v1.y);
    h[3] = __floats2half2_rn(v1.z, v1.w);
    *(uint4*)(d + idx) = *(uint4*)h;
}

__global__ __launch_bounds__(256) void cvt16_kernel(
    const float* __restrict__ src, __half* __restrict__ dst, int n)
{
    int i = (blockIdx.x * 256 + threadIdx.x) * 8;
    if (i >= n) return;
    float4 v0 = *(const float4*)(src + i);
    float4 v1 = *(const float4*)(src + i + 4);
    __half2 h[4];
    h[0] = __floats2half2_rn(v0.x, v0.y);
    h[1] = __floats2half2_rn(v0.z, v0.w);
    h[2] = __floats2half2_rn(v1.x, v1.y);
    h[3] = __floats2half2_rn(v1.z, v1.w);
    *(uint4*)(dst + i) = *(uint4*)h;
}

__global__ __launch_bounds__(256) void tsplit16_kernel(
    const float* __restrict__ W, __half* __restrict__ hi, __half* __restrict__ lo)
{
    __shared__ float t[32][33];
    const int o0 = blockIdx.y * 32, i0 = blockIdx.x * 32;
    const int c = threadIdx.x & 31;
    const int r0 = threadIdx.x >> 5;
#pragma unroll
    for (int it = 0; it < 4; it++) {
        int r = r0 + it * 8;
        t[r][c] = W[(size_t)(o0 + r) * 1024 + i0 + c];
    }
    __syncthreads();
#pragma unroll
    for (int it = 0; it < 4; it++) {
        int r = r0 + it * 8;
        float v = t[c][r];
        __half h = __float2half_rn(v);
        size_t idx = (size_t)(i0 + r) * 1024 + o0 + c;
        hi[idx] = h;
        lo[idx] = __float2half_rn(v - __half2float(h));
    }
}

// ---------------------------------------------------------------------------
// p_attn core + edges fused. grid (32 bh, 16 s-split), block 256.
// ---------------------------------------------------------------------------
__global__ __launch_bounds__(256) void pa_core_mma(
    const __half* __restrict__ k16, const __half* __restrict__ vh16,
    const float* __restrict__ pos, float* __restrict__ pa)
{
    __shared__ __half Ks[32 * 136];
    __shared__ __half Vh[32 * 136];
    __shared__ float ps[32];

    const int bh = blockIdx.x;
    const int b = bh >> 3;
    const int sp = blockIdx.y;
    const int tid = threadIdx.x;
    const int wid = tid >> 5, lane = tid & 31;
    const int warp_row = wid >> 2;
    const int warp_col = wid & 3;

    const uint32_t ksb = smem_u32(Ks);
    const uint32_t vhb = smem_u32(Vh);

    const size_t gbase = ((size_t)bh * NS + sp * 512) * NDK;
    const float* posb = pos + (size_t)b * NS + sp * 512;

    float acc[4][4][4];
#pragma unroll
    for (int mi = 0; mi < 4; mi++)
#pragma unroll
        for (int ni = 0; ni < 4; ni++)
#pragma unroll
            for (int q = 0; q < 4; q++) acc[mi][ni][q] = 0.f;

    float eacc = 0.f;
    float p2 = 0.f;

    const int aRow = (lane & 7) | ((lane >> 4) << 3);
    const int aCol = ((lane >> 3) & 1) << 3;
    const int bRow = (lane & 7) | (((lane >> 3) & 1) << 3);
    const int bCol = ((lane >> 4) & 1) << 3;
    const int ecol = tid & 127;

    for (int s0 = 0; s0 < 512; s0 += 32) {
#pragma unroll
        for (int it = 0; it < 2; it++) {
            int f = tid + it * 256;
            int row = f >> 4;
            int c8 = (f & 15) * 8;
            size_t ga = gbase + (size_t)(s0 + row) * NDK + c8;
            int so = row * 136 + c8;
            *(float4*)(Ks + so) = *(const float4*)(k16 + ga);
            *(float4*)(Vh + so) = *(const float4*)(vh16 + ga);
        }
        if (tid < 32) ps[tid] = posb[s0 + tid];
        __syncthreads();

#pragma unroll
        for (int ki = 0; ki < 2; ki++) {
            const int kio = ki * 16;
            uint32_t af[4][4], bhi[4][2];
#pragma unroll
            for (int mi = 0; mi < 4; mi++) {
                int mcol = warp_row * 64 + mi * 16 + aCol;
                ldsm4t(af[mi], ksb + (kio + aRow) * 272 + mcol * 2);
            }
#pragma unroll
            for (int g = 0; g < 2; g++) {
                int ec = warp_col * 32 + g * 16 + bCol;
                uint32_t tr[4];
                ldsm4t(tr, vhb + (kio + bRow) * 272 + ec * 2);
                bhi[2 * g][0] = tr[0]; bhi[2 * g][1] = tr[1];
                bhi[2 * g + 1][0] = tr[2]; bhi[2 * g + 1][1] = tr[3];
            }
#pragma unroll
            for (int mi = 0; mi < 4; mi++)
#pragma unroll
                for (int ni = 0; ni < 4; ni++)
                    mma_f16(acc[mi][ni], af[mi], bhi[ni]);
        }

        if (tid < 128) {
#pragma unroll 8
            for (int r = 0; r < 32; r++)
                eacc = fmaf(ps[r], __half2float(Vh[r * 136 + ecol]), eacc);
        } else {
#pragma unroll 8
            for (int r = 0; r < 32; r++)
                eacc = fmaf(ps[r], __half2float(Ks[r * 136 + ecol]), eacc);
        }
        if (wid == 0) { float pv = ps[lane]; p2 = fmaf(pv, pv, p2); }
        __syncthreads();
    }

    const float invS = 1.0f / (float)NS;
    float* pab = pa + (size_t)bh * NE * NE;
#pragma unroll
    for (int mi = 0; mi < 4; mi++) {
        int d0 = warp_row * 64 + mi * 16 + (lane >> 2);
#pragma unroll
        for (int ni = 0; ni < 4; ni++) {
            int e0 = warp_col * 32 + ni * 8 + (lane & 3) * 2;
            atomicAdd(&pab[(1 + d0) * NE + 1 + e0],     acc[mi][ni][0] * invS);
            atomicAdd(&pab[(1 + d0) * NE + 2 + e0],     acc[mi][ni][1] * invS);
            atomicAdd(&pab[(1 + d0 + 8) * NE + 1 + e0], acc[mi][ni][2] * invS);
            atomicAdd(&pab[(1 + d0 + 8) * NE + 2 + e0], acc[mi][ni][3] * invS);
        }
    }
    if (tid < 128) atomicAdd(&pab[0 * NE + 1 + ecol], eacc * invS);
    else           atomicAdd(&pab[(1 + ecol) * NE + 0], eacc * invS);
    if (wid == 0) {
#pragma unroll
        for (int o = 16; o > 0; o >>= 1)
            p2 += __shfl_xor_sync(0xffffffffu, p2, o);
        if (lane == 0) atomicAdd(&pab[0], p2 * invS);
    }
}

// ---------------------------------------------------------------------------
// Gd (fp16 hi/lo) = pa @ Wfc_h^T; outer-product, e-major smem (R13 version).
// grid (8 ntile, 8 h, 4 b), 256 threads as 16x16; 4 (pass_n x pass_d) passes.
// ---------------------------------------------------------------------------
__global__ __launch_bounds__(256) void g_kernel(
    const float* __restrict__ pa, const float* __restrict__ Wfc,
    __half* __restrict__ gdh, __half* __restrict__ gdl, float* __restrict__ gpos)
{
    extern __shared__ float sm[];
    float* pat = sm;                  // [129 e][132 d-stride]
    float* wt  = sm + 129 * 132;      // [129 e][132 n-stride]

    const int nt = blockIdx.x, h = blockIdx.y, b = blockIdx.z;
    const int tid = threadIdx.x;
    const int n0 = nt * 128;
    const int ty = tid >> 4, tx = tid & 15;

    const float* pab = pa + ((size_t)(b * NH + h)) * NE * NE;
    for (int i = tid; i < NE * NE; i += 256) {
        int d = i / NE, e = i - d * NE;
        pat[e * 132 + d] = pab[i];
    }
    for (int i = tid; i < 128 * NE; i += 256) {
        int n = i / NE, e = i - n * NE;
        wt[e * 132 + n] = Wfc[(size_t)(n0 + n) * KFC + h * NE + e];
    }
    __syncthreads();

#pragma unroll
    for (int pn = 0; pn < 2; pn++) {
#pragma unroll
        for (int pd = 0; pd < 2; pd++) {
            const int nn = pn * 64 + ty * 4;
            const int dd = pd * 64 + tx * 4;
            float acc[4][4];
#pragma unroll
            for (int i = 0; i < 4; i++)
#pragma unroll
                for (int j = 0; j < 4; j++) acc[i][j] = 0.f;

            for (int e = 0; e < NE; e++) {
                float4 a = *(const float4*)(wt + e * 132 + nn);
                float4 p = *(const float4*)(pat + e * 132 + dd);
                float ar[4] = {a.x, a.y, a.z, a.w};
                float pr[4] = {p.x, p.y, p.z, p.w};
#pragma unroll
                for (int i = 0; i < 4; i++)
#pragma unroll
                    for (int j = 0; j < 4; j++)
                        acc[i][j] = fmaf(ar[i], pr[j], acc[i][j]);
            }

#pragma unroll
            for (int i = 0; i < 4; i++) {
                int n = nn + i;
#pragma unroll
                for (int j = 0; j < 4; j++) {
                    int d = dd + j;
                    float v = acc[i][j];
                    if (d == 0) {
                        atomicAdd(&gpos[b * 1024 + n0 + n], v);
                    } else {
                        size_t idx = ((size_t)b * 1024 + n0 + n) * 1024
                                     + h * NDK + d - 1;
                        __half hh = __float2half_rn(v);
                        gdh[idx] = hh;
                        gdl[idx] = __float2half_rn(v - __half2float(hh));
                    }
                }
            }
        }
    }

    // d = 128 column (last of 129)
    if (tid < 128) {
        int n = tid;
        float accv = 0.f;
        for (int e = 0; e < NE; e++)
            accv = fmaf(wt[e * 132 + n], pat[e * 132 + 128], accv);
        size_t idx = ((size_t)b * 1024 + n0 + n) * 1024 + h * NDK + 127;
        __half hh = __float2half_rn(accv);
        gdh[idx] = hh;
        gdl[idx] = __float2half_rn(accv - __half2float(hh));
    }
}

// ---------------------------------------------------------------------------
__global__ __launch_bounds__(256) void bias2_kernel(
    const __half* __restrict__ gdh, const __half* __restrict__ gdl,
    const float* __restrict__ bq, const float* __restrict__ bfc,
    float* __restrict__ bias2)
{
    const int n = blockIdx.x, b = blockIdx.y;
    const int tid = threadIdx.x;
    size_t base = ((size_t)b * 1024 + n) * 1024;
    float acc = 0.f;
    for (int o = tid; o < 1024; o += 256) {
        float v = __half2float(gdh[base + o]) + __half2float(gdl[base + o]);
        acc = fmaf(bq[o], v, acc);
    }
    __shared__ float red[256];
    red[tid] = acc;
    __syncthreads();
    for (int o = 128; o > 0; o >>= 1) {
        if (tid < o) red[tid] += red[tid + o];
        __syncthreads();
    }
    if (tid == 0) bias2[b * 1024 + n] = red[0] + bfc[n];
}

// ============================ host side ====================================
typedef CUresult (*EncodeFn)(CUtensorMap*, CUtensorMapDataType, cuuint32_t, void*,
                             const cuuint64_t*, const cuuint64_t*, const cuuint32_t*,
                             const cuuint32_t*, CUtensorMapInterleave, CUtensorMapSwizzle,
                             CUtensorMapL2promotion, CUtensorMapFloatOOBfill);

static EncodeFn get_encode() {
    static EncodeFn fn = nullptr;
    if (!fn) {
        void* p = nullptr;
        cudaDriverEntryPointQueryResult st;
        cudaGetDriverEntryPoint("cuTensorMapEncodeTiled", &p, cudaEnableDefault, &st);
        fn = (EncodeFn)p;
    }
    return fn;
}

static void encode_f16(CUtensorMap* m, const void* base,
                       uint64_t kdim, uint64_t rows, uint64_t nz, uint32_t boxRows) {
    cuuint64_t dims[3]    = { kdim, rows, nz };
    cuuint64_t strides[2] = { kdim * 2, rows * kdim * 2 };
    cuuint32_t box[3]     = { 64, boxRows, 1 };
    cuuint32_t est[3]     = { 1, 1, 1 };
    get_encode()(m, CU_TENSOR_MAP_DATA_TYPE_FLOAT16, 3, (void*)base,
                 dims, strides, box, est,
                 CU_TENSOR_MAP_INTERLEAVE_NONE, CU_TENSOR_MAP_SWIZZLE_128B,
                 CU_TENSOR_MAP_L2_PROMOTION_L2_128B, CU_TENSOR_MAP_FLOAT_OOB_FILL_NONE);
}

extern "C" void kernel_launch(void* const* d_in, const int* in_sizes, int n_in,
                              void* d_out, int out_size)
{
    (void)in_sizes; (void)n_in; (void)out_size;
    const float* query = (const float*)d_in[0];
    const float* key   = (const float*)d_in[1];
    const float* value = (const float*)d_in[2];
    const float* pos   = (const float*)d_in[3];
    const float* Wq    = (const float*)d_in[4];
    const float* bq    = (const float*)d_in[5];
    const float* Wk    = (const float*)d_in[6];
    const float* bk    = (const float*)d_in[7];
    const float* Wv    = (const float*)d_in[8];
    const float* bv    = (const float*)d_in[9];
    const float* gK    = (const float*)d_in[10];
    const float* betaK = (const float*)d_in[11];
    const float* gV    = (const float*)d_in[12];
    const float* betaV = (const float*)d_in[13];
    const float* Wfc   = (const float*)d_in[14];
    const float* bfc   = (const float*)d_in[15];
    float* out = (float*)d_out;

    float *pa, *gpos, *bias2;
    __half *a16, *c16, *bh16, *bl16, *k16, *vh16, *wc16;
    cudaGetSymbolAddress((void**)&pa, g_pa);
    cudaGetSymbolAddress((void**)&gpos, g_gpos);
    cudaGetSymbolAddress((void**)&bias2, g_bias2);
    cudaGetSymbolAddress((void**)&a16, g_a16);
    cudaGetSymbolAddress((void**)&c16, g_c16);
    cudaGetSymbolAddress((void**)&bh16, g_bh16);
    cudaGetSymbolAddress((void**)&bl16, g_bl16);
    cudaGetSymbolAddress((void**)&k16, g_k16);
    cudaGetSymbolAddress((void**)&vh16, g_vh16);
    cudaGetSymbolAddress((void**)&wc16, g_wc16);

    cudaFuncSetAttribute(gemm_kv, cudaFuncAttributeMaxDynamicSharedMemorySize,
                         (int)SMEM_KV);
    cudaFuncSetAttribute(gemm_out, cudaFuncAttributeMaxDynamicSharedMemorySize,
                         (int)SMEM_OUT);
    cudaFuncSetAttribute(gemm_mma3, cudaFuncAttributeMaxDynamicSharedMemorySize,
                         (int)SMEM3_DYN);
    cudaFuncSetAttribute(g_kernel, cudaFuncAttributeMaxDynamicSharedMemorySize,
                         (129 + 129) * 132 * (int)sizeof(float));

    CUtensorMap tAK, tAV, tBkv, tGh, tGl, tWqh, tWql, tAq, tWc;
    encode_f16(&tAK, a16, 1024, 32768, 1, 128);
    encode_f16(&tAV, c16, 1024, 32768, 1, 128);
    encode_f16(&tBkv, bh16, 1024, 1024, 2, 256);
    encode_f16(&tGh,  a16,           1024, 1024, 4, 128);
    encode_f16(&tGl,  a16 + 4194304, 1024, 1024, 4, 128);
    encode_f16(&tWqh, bh16, 1024, 1024, 1, 128);
    encode_f16(&tWql, bl16, 1024, 1024, 1, 128);
    encode_f16(&tAq,  a16,  1024, 32768, 1, 128);
    encode_f16(&tWc,  wc16, 1024, 1024, 4, 256);

    const int NA = 33554432, NW = 1048576;

    // Inputs to fp16 (key, value, Wk, Wv in one launch)
    cvt_all_kernel<<<33792, 256>>>(key, a16, value, c16,
                                   Wk, bh16, Wv, bh16 + NW);

    // K+V projection with fused per-head LN (BN=256: 2 heads per tile)
    gemm_kv<<<dim3(4, 256, 2), 288, SMEM_KV>>>(
        tAK, tAV, tBkv, bk, bv, gK, betaK, gV, betaV, k16, vh16);

    // p_attn = Kc^T Vc / S  (core + edges fused)
    cudaMemsetAsync(pa, 0, (size_t)32 * NE * NE * sizeof(float));
    pa_core_mma<<<dim3(32, 16), 256>>>(k16, vh16, pos, pa);

    // Gd (fp16 hi/lo directly into a16) + gpos
    cudaMemsetAsync(gpos, 0, 4096 * sizeof(float));
    g_kernel<<<dim3(8, NH, NB), 256, (129 + 129) * 132 * sizeof(float)>>>(
        pa, Wfc, a16, a16 + 4194304, gpos);

    // bias2 = bfc + bq @ (Gd hi+lo)^T
    bias2_kernel<<<dim3(1024, 4), 256>>>(a16, a16 + 4194304, bq, bfc, bias2);

    // Wq^T hi/lo
    tsplit16_kernel<<<dim3(32, 32), 256>>>(Wq, bh16, bl16);

    // Wcomb[b] = Gd[b] @ Wq (3-pass) -> fp16 directly into wc16
    gemm_mma3<<<dim3(8, 8, 4), 256, SMEM3_DYN>>>(tGh, tGl, tWqh, tWql, wc16, 16);

    // query -> fp16 (a16 free after gemm_mma3 consumed Gd)
    cvt16_kernel<<<NA / 2048, 256>>>(query, a16, NA);

    // out[b] = query[b] @ Wcomb[b]^T + pos (x) gpos[b] + bias2[b]  (BN=256)
    gemm_out<<<dim3(4, 64, 4), 288, SMEM_OUT>>>(tAq, tWc, bias2, pos, gpos, out);
}